// round 1
// baseline (speedup 1.0000x reference)
#include <cuda_runtime.h>

// Problem constants (from reference): N=50000 nodes, D=64, E=800000 edges.
#define MAX_NODES 50000
#define DIM 64

// Scratch (device globals — no allocations allowed in kernel_launch).
__device__ float g_emb[MAX_NODES * DIM];
__device__ float g_twohop[MAX_NODES * DIM];

// K1: emb = elu(x * w), zero twohop scratch, zero output.
__global__ void k_emb_and_zero(const float* __restrict__ x,
                               const float* __restrict__ w,
                               float* __restrict__ out,
                               int total) {
    int i = blockIdx.x * blockDim.x + threadIdx.x;
    if (i >= total) return;
    float v = x[i] * w[i & (DIM - 1)];
    g_emb[i] = (v > 0.0f) ? v : expm1f(v);
    g_twohop[i] = 0.0f;
    out[i] = 0.0f;
}

// K2: two-hop scatter. One warp per edge; lane l handles columns [2l, 2l+1].
// twohop[dst] += emb[src] * (1 + [e==0] + [e==4] + [e==5])
__global__ void k_scatter_twohop(const int* __restrict__ src,
                                 const int* __restrict__ dst,
                                 const int* __restrict__ ef,
                                 int n_edges) {
    int gid = blockIdx.x * blockDim.x + threadIdx.x;
    int edge = gid >> 5;
    if (edge >= n_edges) return;
    int lane = gid & 31;

    int s = src[edge];
    int d = dst[edge];
    int t = ef[edge];
    float scale = 1.0f + (float)((t == 0) + (t == 4) + (t == 5));

    float2 v = *reinterpret_cast<const float2*>(g_emb + (size_t)s * DIM + lane * 2);
    float* p = g_twohop + (size_t)d * DIM + lane * 2;
    atomicAdd(p,     v.x * scale);
    atomicAdd(p + 1, v.y * scale);
}

// K3: one-hop scatter for edges of type 3: out[dst] += twohop[src].
__global__ void k_scatter_onehop(const int* __restrict__ src,
                                 const int* __restrict__ dst,
                                 const int* __restrict__ ef,
                                 float* __restrict__ out,
                                 int n_edges) {
    int gid = blockIdx.x * blockDim.x + threadIdx.x;
    int edge = gid >> 5;
    if (edge >= n_edges) return;
    if (ef[edge] != 3) return;
    int lane = gid & 31;

    int s = src[edge];
    int d = dst[edge];

    float2 v = *reinterpret_cast<const float2*>(g_twohop + (size_t)s * DIM + lane * 2);
    float* p = out + (size_t)d * DIM + lane * 2;
    atomicAdd(p,     v.x);
    atomicAdd(p + 1, v.y);
}

extern "C" void kernel_launch(void* const* d_in, const int* in_sizes, int n_in,
                              void* d_out, int out_size) {
    const float* x   = (const float*)d_in[0];   // graph_embedding [N, D]
    const float* w   = (const float*)d_in[1];   // weight [1, D]
    const int*   src = (const int*)d_in[2];     // [E]
    const int*   dst = (const int*)d_in[3];     // [E]
    const int*   ef  = (const int*)d_in[4];     // [E]
    float* out = (float*)d_out;                 // [N, D]

    int total   = in_sizes[0];                  // N * D
    int n_edges = in_sizes[2];                  // E

    // K1: elementwise emb + zeroing (3.2M elems)
    {
        int threads = 256;
        int blocks = (total + threads - 1) / threads;
        k_emb_and_zero<<<blocks, threads>>>(x, w, out, total);
    }

    // K2 + K3: warp-per-edge scatters
    {
        int threads = 256;                       // 8 warps/block
        long long total_threads = (long long)n_edges * 32;
        int blocks = (int)((total_threads + threads - 1) / threads);
        k_scatter_twohop<<<blocks, threads>>>(src, dst, ef, n_edges);
        k_scatter_onehop<<<blocks, threads>>>(src, dst, ef, out, n_edges);
    }
}

// round 2
// speedup vs baseline: 1.6774x; 1.6774x over previous
#include <cuda_runtime.h>

// Problem constants (from reference): N=50000 nodes, D=64, E=800000 edges.
#define MAX_NODES 50000
#define DIM 64

// Scratch (device globals — no allocations allowed in kernel_launch).
__device__ float g_emb[MAX_NODES * DIM];
__device__ float g_twohop[MAX_NODES * DIM];

__device__ __forceinline__ void red_add_v4(float* p, float4 v) {
    asm volatile("red.global.add.v4.f32 [%0], {%1, %2, %3, %4};"
                 :: "l"(p), "f"(v.x), "f"(v.y), "f"(v.z), "f"(v.w)
                 : "memory");
}

// K1: emb = elu(x * w), zero twohop scratch, zero output. float4 per thread.
__global__ void k_emb_and_zero(const float4* __restrict__ x,
                               const float4* __restrict__ w,
                               float4* __restrict__ out,
                               int total4) {
    int i = blockIdx.x * blockDim.x + threadIdx.x;
    if (i >= total4) return;
    float4 xv = x[i];
    float4 wv = w[i & (DIM / 4 - 1)];
    float4 e;
    float a;
    a = xv.x * wv.x; e.x = (a > 0.0f) ? a : expm1f(a);
    a = xv.y * wv.y; e.y = (a > 0.0f) ? a : expm1f(a);
    a = xv.z * wv.z; e.z = (a > 0.0f) ? a : expm1f(a);
    a = xv.w * wv.w; e.w = (a > 0.0f) ? a : expm1f(a);
    reinterpret_cast<float4*>(g_emb)[i] = e;
    reinterpret_cast<float4*>(g_twohop)[i] = make_float4(0.f, 0.f, 0.f, 0.f);
    out[i] = make_float4(0.f, 0.f, 0.f, 0.f);
}

// K2: two-hop scatter. 16 lanes per edge; lane l owns float4 chunk l of the row.
// twohop[dst] += emb[src] * (1 + [e==0] + [e==4] + [e==5])
__global__ void k_scatter_twohop(const int* __restrict__ src,
                                 const int* __restrict__ dst,
                                 const int* __restrict__ ef,
                                 int n_edges) {
    int gid = blockIdx.x * blockDim.x + threadIdx.x;
    int edge = gid >> 4;
    if (edge >= n_edges) return;
    int lane = gid & 15;

    int s = src[edge];
    int d = dst[edge];
    int t = ef[edge];
    float scale = 1.0f + (float)((t == 0) + (t == 4) + (t == 5));

    float4 v = *reinterpret_cast<const float4*>(g_emb + (size_t)s * DIM + lane * 4);
    v.x *= scale; v.y *= scale; v.z *= scale; v.w *= scale;
    red_add_v4(g_twohop + (size_t)d * DIM + lane * 4, v);
}

// K3: one-hop scatter for edges of type 3: out[dst] += twohop[src].
__global__ void k_scatter_onehop(const int* __restrict__ src,
                                 const int* __restrict__ dst,
                                 const int* __restrict__ ef,
                                 float* __restrict__ out,
                                 int n_edges) {
    int gid = blockIdx.x * blockDim.x + threadIdx.x;
    int edge = gid >> 4;
    if (edge >= n_edges) return;
    if (ef[edge] != 3) return;
    int lane = gid & 15;

    int s = src[edge];
    int d = dst[edge];

    float4 v = *reinterpret_cast<const float4*>(g_twohop + (size_t)s * DIM + lane * 4);
    red_add_v4(out + (size_t)d * DIM + lane * 4, v);
}

extern "C" void kernel_launch(void* const* d_in, const int* in_sizes, int n_in,
                              void* d_out, int out_size) {
    const float* x   = (const float*)d_in[0];   // graph_embedding [N, D]
    const float* w   = (const float*)d_in[1];   // weight [1, D]
    const int*   src = (const int*)d_in[2];     // [E]
    const int*   dst = (const int*)d_in[3];     // [E]
    const int*   ef  = (const int*)d_in[4];     // [E]
    float* out = (float*)d_out;                 // [N, D]

    int total   = in_sizes[0];                  // N * D
    int n_edges = in_sizes[2];                  // E
    int total4  = total / 4;

    // K1: elementwise emb + zeroing (float4-vectorized)
    {
        int threads = 256;
        int blocks = (total4 + threads - 1) / threads;
        k_emb_and_zero<<<blocks, threads>>>((const float4*)x, (const float4*)w,
                                            (float4*)out, total4);
    }

    // K2 + K3: 16-lanes-per-edge scatters with v4 RED
    {
        int threads = 256;                       // 16 edges/block
        long long total_threads = (long long)n_edges * 16;
        int blocks = (int)((total_threads + threads - 1) / threads);
        k_scatter_twohop<<<blocks, threads>>>(src, dst, ef, n_edges);
        k_scatter_onehop<<<blocks, threads>>>(src, dst, ef, out, n_edges);
    }
}

// round 3
// speedup vs baseline: 2.1941x; 1.3080x over previous
#include <cuda_runtime.h>

// Problem constants: N=50000 nodes, D=64, E=800000 edges.
#define MAX_NODES   50000
#define MAX_EDGES   800000
#define DIM         64
#define SCAN_TPB    1024
#define MAX_SBLK    ((MAX_NODES + SCAN_TPB - 1) / SCAN_TPB)   // 49
#define NPAD        (MAX_SBLK * SCAN_TPB)                      // 50176

// Device-global scratch (no allocations allowed).
__device__ float g_emb[MAX_NODES * DIM];
__device__ float g_twohop[MAX_NODES * DIM];
__device__ int   g_cntA[NPAD];
__device__ int   g_cntB[NPAD];
__device__ int   g_baseA[NPAD];
__device__ int   g_baseB[NPAD];
__device__ int   g_curA[NPAD];
__device__ int   g_curB[NPAD];
__device__ int   g_bsum[2 * MAX_SBLK];
__device__ int   g_eA[MAX_EDGES];   // packed: (src << 1) | (scale == 2)
__device__ int   g_eB[MAX_EDGES];   // src for e==3 edges

// K1: emb = elu(x*w) (float4), zero CSR counters.
__global__ void k_emb_and_zero(const float4* __restrict__ x,
                               const float4* __restrict__ w,
                               int total4, int npad) {
    int i = blockIdx.x * blockDim.x + threadIdx.x;
    if (i < total4) {
        float4 xv = x[i];
        float4 wv = w[i & (DIM / 4 - 1)];
        float4 e; float a;
        a = xv.x * wv.x; e.x = (a > 0.0f) ? a : expm1f(a);
        a = xv.y * wv.y; e.y = (a > 0.0f) ? a : expm1f(a);
        a = xv.z * wv.z; e.z = (a > 0.0f) ? a : expm1f(a);
        a = xv.w * wv.w; e.w = (a > 0.0f) ? a : expm1f(a);
        reinterpret_cast<float4*>(g_emb)[i] = e;
    }
    if (i < npad) {
        g_cntA[i] = 0; g_cntB[i] = 0;
        g_curA[i] = 0; g_curB[i] = 0;
    }
}

// K2: per-dst degree counts (both CSRs).
__global__ void k_count(const int* __restrict__ dst,
                        const int* __restrict__ ef,
                        int n_edges) {
    int e = blockIdx.x * blockDim.x + threadIdx.x;
    if (e >= n_edges) return;
    int d = dst[e];
    atomicAdd(&g_cntA[d], 1);
    if (ef[e] == 3) atomicAdd(&g_cntB[d], 1);
}

// K3: per-block exclusive scan of counts; emit block totals.
__global__ void k_scan1(int nblk) {
    __shared__ int sh[SCAN_TPB];
    int which = blockIdx.x / nblk;                // 0 = A, 1 = B
    int blk   = blockIdx.x - which * nblk;
    int idx   = blk * SCAN_TPB + threadIdx.x;
    const int* cnt = which ? g_cntB : g_cntA;
    int* base      = which ? g_baseB : g_baseA;

    int v = cnt[idx];
    sh[threadIdx.x] = v;
    __syncthreads();
    #pragma unroll
    for (int off = 1; off < SCAN_TPB; off <<= 1) {
        int t = (threadIdx.x >= off) ? sh[threadIdx.x - off] : 0;
        __syncthreads();
        sh[threadIdx.x] += t;
        __syncthreads();
    }
    base[idx] = sh[threadIdx.x] - v;              // exclusive within block
    if (threadIdx.x == SCAN_TPB - 1)
        g_bsum[which * nblk + blk] = sh[threadIdx.x];
}

// K4: add cross-block offsets (each block serially prefixes <=49 sums).
__global__ void k_scan2(int nblk) {
    __shared__ int off_sh;
    int which = blockIdx.x / nblk;
    int blk   = blockIdx.x - which * nblk;
    if (threadIdx.x == 0) {
        int off = 0;
        for (int j = 0; j < blk; j++) off += g_bsum[which * nblk + j];
        off_sh = off;
    }
    __syncthreads();
    int idx = blk * SCAN_TPB + threadIdx.x;
    if (which) g_baseB[idx] += off_sh;
    else       g_baseA[idx] += off_sh;
}

// K5: place edges into CSR slots.
__global__ void k_place(const int* __restrict__ src,
                        const int* __restrict__ dst,
                        const int* __restrict__ ef,
                        int n_edges) {
    int e = blockIdx.x * blockDim.x + threadIdx.x;
    if (e >= n_edges) return;
    int s = src[e], d = dst[e], t = ef[e];
    int two = (t == 0) | (t == 4) | (t == 5);
    int pos = g_baseA[d] + atomicAdd(&g_curA[d], 1);
    g_eA[pos] = (s << 1) | two;
    if (t == 3) {
        int posb = g_baseB[d] + atomicAdd(&g_curB[d], 1);
        g_eB[posb] = s;
    }
}

// K6: pull two-hop. 16 lanes per node, each lane owns one float4 of the row.
__global__ void k_gather_twohop(int n_nodes) {
    int gid  = blockIdx.x * blockDim.x + threadIdx.x;
    int node = gid >> 4;
    if (node >= n_nodes) return;
    int lane = gid & 15;
    int base = g_baseA[node];
    int cnt  = g_cntA[node];
    float4 acc = make_float4(0.f, 0.f, 0.f, 0.f);
    #pragma unroll 4
    for (int k = 0; k < cnt; k++) {
        int packed = g_eA[base + k];
        float scale = 1.0f + (float)(packed & 1);
        int s = packed >> 1;
        float4 v = *reinterpret_cast<const float4*>(g_emb + (size_t)s * DIM + lane * 4);
        acc.x += v.x * scale; acc.y += v.y * scale;
        acc.z += v.z * scale; acc.w += v.w * scale;
    }
    *reinterpret_cast<float4*>(g_twohop + (size_t)node * DIM + lane * 4) = acc;
}

// K7: pull one-hop (e==3): out[node] = sum twohop[src]. Writes every row.
__global__ void k_gather_onehop(float* __restrict__ out, int n_nodes) {
    int gid  = blockIdx.x * blockDim.x + threadIdx.x;
    int node = gid >> 4;
    if (node >= n_nodes) return;
    int lane = gid & 15;
    int base = g_baseB[node];
    int cnt  = g_cntB[node];
    float4 acc = make_float4(0.f, 0.f, 0.f, 0.f);
    #pragma unroll 4
    for (int k = 0; k < cnt; k++) {
        int s = g_eB[base + k];
        float4 v = *reinterpret_cast<const float4*>(g_twohop + (size_t)s * DIM + lane * 4);
        acc.x += v.x; acc.y += v.y; acc.z += v.z; acc.w += v.w;
    }
    *reinterpret_cast<float4*>(out + (size_t)node * DIM + lane * 4) = acc;
}

extern "C" void kernel_launch(void* const* d_in, const int* in_sizes, int n_in,
                              void* d_out, int out_size) {
    const float* x   = (const float*)d_in[0];   // graph_embedding [N, D]
    const float* w   = (const float*)d_in[1];   // weight [1, D]
    const int*   src = (const int*)d_in[2];     // [E]
    const int*   dst = (const int*)d_in[3];     // [E]
    const int*   ef  = (const int*)d_in[4];     // [E]
    float* out = (float*)d_out;                 // [N, D]

    int total   = in_sizes[0];                  // N * D
    int n_edges = in_sizes[2];                  // E
    int n_nodes = total / DIM;
    int total4  = total / 4;
    int nblk    = (n_nodes + SCAN_TPB - 1) / SCAN_TPB;
    int npad    = nblk * SCAN_TPB;

    const int T = 256;

    // K1: emb + zero counters
    {
        int work = (total4 > npad) ? total4 : npad;
        k_emb_and_zero<<<(work + T - 1) / T, T>>>((const float4*)x,
                                                  (const float4*)w, total4, npad);
    }
    // K2: count
    k_count<<<(n_edges + T - 1) / T, T>>>(dst, ef, n_edges);
    // K3/K4: scan (both CSRs)
    k_scan1<<<2 * nblk, SCAN_TPB>>>(nblk);
    k_scan2<<<2 * nblk, SCAN_TPB>>>(nblk);
    // K5: placement
    k_place<<<(n_edges + T - 1) / T, T>>>(src, dst, ef, n_edges);
    // K6/K7: pull gathers (16 lanes per node)
    {
        int threads = n_nodes * 16;
        k_gather_twohop<<<(threads + T - 1) / T, T>>>(n_nodes);
        k_gather_onehop<<<(threads + T - 1) / T, T>>>(out, n_nodes);
    }
}

// round 4
// speedup vs baseline: 2.3540x; 1.0729x over previous
#include <cuda_runtime.h>

// Problem constants: N=50000 nodes, D=64, E=800000 edges.
#define MAX_NODES   50000
#define MAX_EDGES   800000
#define DIM         64
#define SCAN_TPB    1024
#define MAX_SBLK    ((MAX_NODES + SCAN_TPB - 1) / SCAN_TPB)   // 49
#define NPAD        (MAX_SBLK * SCAN_TPB)                      // 50176

// Device-global scratch (no allocations allowed).
__device__ float g_emb[MAX_NODES * DIM];
__device__ float g_twohop[MAX_NODES * DIM];
__device__ int   g_cnt[2 * NPAD];       // [0:NPAD)=A counts, [NPAD:2*NPAD)=B counts
__device__ int   g_baseA[NPAD];
__device__ int   g_baseB[NPAD];
__device__ int   g_curA[NPAD];
__device__ int   g_curB[NPAD];
__device__ int   g_bsum[2 * MAX_SBLK];
__device__ int   g_eA[MAX_EDGES];       // packed: (src << 1) | (scale == 2)
__device__ int   g_eB[MAX_EDGES];       // src for e==3 edges

// K1: emb = elu(x*w) (float4 per thread) + per-dst degree counting fused.
// Requires g_cnt zeroed beforehand (memset node).
__global__ void k_emb_count(const float4* __restrict__ x,
                            const float4* __restrict__ w,
                            const int* __restrict__ dst,
                            const int* __restrict__ ef,
                            int total4, int n_edges) {
    int i = blockIdx.x * blockDim.x + threadIdx.x;
    if (i < total4) {
        float4 xv = x[i];
        float4 wv = w[i & (DIM / 4 - 1)];
        float4 e; float a;
        a = xv.x * wv.x; e.x = (a > 0.0f) ? a : expm1f(a);
        a = xv.y * wv.y; e.y = (a > 0.0f) ? a : expm1f(a);
        a = xv.z * wv.z; e.z = (a > 0.0f) ? a : expm1f(a);
        a = xv.w * wv.w; e.w = (a > 0.0f) ? a : expm1f(a);
        reinterpret_cast<float4*>(g_emb)[i] = e;
    }
    if (i < n_edges) {
        int d = dst[i];
        atomicAdd(&g_cnt[d], 1);
        if (ef[i] == 3) atomicAdd(&g_cnt[NPAD + d], 1);
    }
}

// K2: per-block exclusive scan (shuffle-based), emit block totals.
__global__ void k_scan1(int nblk) {
    __shared__ int warp_sums[32];
    int which = (blockIdx.x >= nblk) ? 1 : 0;
    int blk   = blockIdx.x - which * nblk;
    int idx   = blk * SCAN_TPB + threadIdx.x;
    int lane  = threadIdx.x & 31;
    int wid   = threadIdx.x >> 5;

    int v = g_cnt[which * NPAD + idx];
    // warp-inclusive scan
    int xi = v;
    #pragma unroll
    for (int o = 1; o < 32; o <<= 1) {
        int t = __shfl_up_sync(0xFFFFFFFFu, xi, o);
        if (lane >= o) xi += t;
    }
    if (lane == 31) warp_sums[wid] = xi;
    __syncthreads();
    if (wid == 0) {
        int s = warp_sums[lane];
        int y = s;
        #pragma unroll
        for (int o = 1; o < 32; o <<= 1) {
            int t = __shfl_up_sync(0xFFFFFFFFu, y, o);
            if (lane >= o) y += t;
        }
        warp_sums[lane] = y - s;                 // exclusive warp offsets
        if (lane == 31) g_bsum[which * nblk + blk] = y;  // block total
    }
    __syncthreads();
    int b = xi - v + warp_sums[wid];             // exclusive within block
    if (which) g_baseB[idx] = b;
    else       g_baseA[idx] = b;
}

// K3: add cross-block offsets (parallel reduce of block sums) and init cur=base.
__global__ void k_scan2(int nblk) {
    __shared__ int sh[64];
    int which = (blockIdx.x >= nblk) ? 1 : 0;
    int blk   = blockIdx.x - which * nblk;
    int t     = threadIdx.x;

    if (t < 64) sh[t] = (t < blk) ? g_bsum[which * nblk + t] : 0;
    __syncthreads();
    if (t < 32) {
        int a = sh[t] + sh[t + 32];
        #pragma unroll
        for (int o = 16; o > 0; o >>= 1) a += __shfl_down_sync(0xFFFFFFFFu, a, o);
        if (t == 0) sh[0] = a;
    }
    __syncthreads();
    int off = sh[0];

    int idx = blk * SCAN_TPB + t;
    if (which) {
        int b = g_baseB[idx] + off;
        g_baseB[idx] = b;
        g_curB[idx]  = b;
    } else {
        int b = g_baseA[idx] + off;
        g_baseA[idx] = b;
        g_curA[idx]  = b;
    }
}

// K4: place edges into CSR slots (cursor pre-initialized to base).
__global__ void k_place(const int* __restrict__ src,
                        const int* __restrict__ dst,
                        const int* __restrict__ ef,
                        int n_edges) {
    int e = blockIdx.x * blockDim.x + threadIdx.x;
    if (e >= n_edges) return;
    int s = src[e], d = dst[e], t = ef[e];
    int two = (t == 0) | (t == 4) | (t == 5);
    int pos = atomicAdd(&g_curA[d], 1);
    g_eA[pos] = (s << 1) | two;
    if (t == 3) {
        int posb = atomicAdd(&g_curB[d], 1);
        g_eB[posb] = s;
    }
}

// K5: pull two-hop. 16 lanes per node, each lane owns one float4 of the row.
__global__ void k_gather_twohop(int n_nodes) {
    int gid  = blockIdx.x * blockDim.x + threadIdx.x;
    int node = gid >> 4;
    if (node >= n_nodes) return;
    int lane = gid & 15;
    int base = g_baseA[node];
    int cnt  = g_cnt[node];
    float4 acc = make_float4(0.f, 0.f, 0.f, 0.f);
    #pragma unroll 4
    for (int k = 0; k < cnt; k++) {
        int packed = g_eA[base + k];
        float scale = 1.0f + (float)(packed & 1);
        int s = packed >> 1;
        float4 v = *reinterpret_cast<const float4*>(g_emb + (size_t)s * DIM + lane * 4);
        acc.x += v.x * scale; acc.y += v.y * scale;
        acc.z += v.z * scale; acc.w += v.w * scale;
    }
    *reinterpret_cast<float4*>(g_twohop + (size_t)node * DIM + lane * 4) = acc;
}

// K6: pull one-hop (e==3): out[node] = sum twohop[src]. Writes every row.
__global__ void k_gather_onehop(float* __restrict__ out, int n_nodes) {
    int gid  = blockIdx.x * blockDim.x + threadIdx.x;
    int node = gid >> 4;
    if (node >= n_nodes) return;
    int lane = gid & 15;
    int base = g_baseB[node];
    int cnt  = g_cnt[NPAD + node];
    float4 acc = make_float4(0.f, 0.f, 0.f, 0.f);
    #pragma unroll 4
    for (int k = 0; k < cnt; k++) {
        int s = g_eB[base + k];
        float4 v = *reinterpret_cast<const float4*>(g_twohop + (size_t)s * DIM + lane * 4);
        acc.x += v.x; acc.y += v.y; acc.z += v.z; acc.w += v.w;
    }
    *reinterpret_cast<float4*>(out + (size_t)node * DIM + lane * 4) = acc;
}

extern "C" void kernel_launch(void* const* d_in, const int* in_sizes, int n_in,
                              void* d_out, int out_size) {
    const float* x   = (const float*)d_in[0];   // graph_embedding [N, D]
    const float* w   = (const float*)d_in[1];   // weight [1, D]
    const int*   src = (const int*)d_in[2];     // [E]
    const int*   dst = (const int*)d_in[3];     // [E]
    const int*   ef  = (const int*)d_in[4];     // [E]
    float* out = (float*)d_out;                 // [N, D]

    int total   = in_sizes[0];                  // N * D
    int n_edges = in_sizes[2];                  // E
    int n_nodes = total / DIM;
    int total4  = total / 4;
    int nblk    = (n_nodes + SCAN_TPB - 1) / SCAN_TPB;

    const int T = 256;

    // Zero counters via a memset node (no kernel needed).
    void* cnt_ptr = nullptr;
    cudaGetSymbolAddress(&cnt_ptr, g_cnt);
    cudaMemsetAsync(cnt_ptr, 0, 2 * NPAD * sizeof(int));

    // K1: emb + fused edge counting
    {
        int work = (total4 > n_edges) ? total4 : n_edges;
        k_emb_count<<<(work + T - 1) / T, T>>>((const float4*)x, (const float4*)w,
                                               dst, ef, total4, n_edges);
    }
    // K2/K3: scan (both CSRs)
    k_scan1<<<2 * nblk, SCAN_TPB>>>(nblk);
    k_scan2<<<2 * nblk, SCAN_TPB>>>(nblk);
    // K4: placement
    k_place<<<(n_edges + T - 1) / T, T>>>(src, dst, ef, n_edges);
    // K5/K6: pull gathers (16 lanes per node)
    {
        int threads = n_nodes * 16;
        k_gather_twohop<<<(threads + T - 1) / T, T>>>(n_nodes);
        k_gather_onehop<<<(threads + T - 1) / T, T>>>(out, n_nodes);
    }
}

// round 5
// speedup vs baseline: 2.3635x; 1.0040x over previous
#include <cuda_runtime.h>

// Problem constants: N=50000 nodes, D=64, E=800000 edges.
#define MAX_NODES   50000
#define MAX_EDGES   800000
#define DIM         64
#define SCAN_TPB    1024
#define MAX_SBLK    ((MAX_NODES + SCAN_TPB - 1) / SCAN_TPB)   // 49
#define NPAD        (MAX_SBLK * SCAN_TPB)                      // 50176

// Device-global scratch (no allocations allowed).
__device__ float g_emb[MAX_NODES * DIM];
__device__ float g_twohop[MAX_NODES * DIM];
__device__ int   g_cnt[2 * NPAD];       // [0:NPAD)=A counts, [NPAD:2*NPAD)=B counts
__device__ int   g_baseA[NPAD];
__device__ int   g_baseB[NPAD];
__device__ int   g_bsum[2 * MAX_SBLK];
__device__ int   g_rank[MAX_EDGES];     // low 16: rank within dst (A); high 16: rank (B)
__device__ int   g_eA[MAX_EDGES];       // packed: (src << 1) | (scale == 2)
__device__ int   g_eB[MAX_EDGES];       // src for e==3 edges

// K1: emb = elu(x*w) (float4 per thread) + fused per-dst counting WITH rank capture.
// Requires g_cnt zeroed beforehand (memset node).
__global__ void k_emb_count(const float4* __restrict__ x,
                            const float4* __restrict__ w,
                            const int* __restrict__ dst,
                            const int* __restrict__ ef,
                            int total4, int n_edges) {
    int i = blockIdx.x * blockDim.x + threadIdx.x;
    if (i < total4) {
        float4 xv = x[i];
        float4 wv = w[i & (DIM / 4 - 1)];
        float4 e; float a;
        a = xv.x * wv.x; e.x = (a > 0.0f) ? a : expm1f(a);
        a = xv.y * wv.y; e.y = (a > 0.0f) ? a : expm1f(a);
        a = xv.z * wv.z; e.z = (a > 0.0f) ? a : expm1f(a);
        a = xv.w * wv.w; e.w = (a > 0.0f) ? a : expm1f(a);
        reinterpret_cast<float4*>(g_emb)[i] = e;
    }
    if (i < n_edges) {
        int d = dst[i];
        int r = atomicAdd(&g_cnt[d], 1);          // A-rank
        if (ef[i] == 3)
            r |= atomicAdd(&g_cnt[NPAD + d], 1) << 16;  // B-rank
        g_rank[i] = r;
    }
}

// K2: per-block exclusive scan (shuffle-based), emit block totals.
__global__ void k_scan1(int nblk) {
    __shared__ int warp_sums[32];
    int which = (blockIdx.x >= nblk) ? 1 : 0;
    int blk   = blockIdx.x - which * nblk;
    int idx   = blk * SCAN_TPB + threadIdx.x;
    int lane  = threadIdx.x & 31;
    int wid   = threadIdx.x >> 5;

    int v = g_cnt[which * NPAD + idx];
    int xi = v;
    #pragma unroll
    for (int o = 1; o < 32; o <<= 1) {
        int t = __shfl_up_sync(0xFFFFFFFFu, xi, o);
        if (lane >= o) xi += t;
    }
    if (lane == 31) warp_sums[wid] = xi;
    __syncthreads();
    if (wid == 0) {
        int s = warp_sums[lane];
        int y = s;
        #pragma unroll
        for (int o = 1; o < 32; o <<= 1) {
            int t = __shfl_up_sync(0xFFFFFFFFu, y, o);
            if (lane >= o) y += t;
        }
        warp_sums[lane] = y - s;                 // exclusive warp offsets
        if (lane == 31) g_bsum[which * nblk + blk] = y;  // block total
    }
    __syncthreads();
    int b = xi - v + warp_sums[wid];             // exclusive within block
    if (which) g_baseB[idx] = b;
    else       g_baseA[idx] = b;
}

// K3: add cross-block offsets (parallel reduce of block sums).
__global__ void k_scan2(int nblk) {
    __shared__ int sh[64];
    int which = (blockIdx.x >= nblk) ? 1 : 0;
    int blk   = blockIdx.x - which * nblk;
    int t     = threadIdx.x;

    if (t < 64) sh[t] = (t < blk) ? g_bsum[which * nblk + t] : 0;
    __syncthreads();
    if (t < 32) {
        int a = sh[t] + sh[t + 32];
        #pragma unroll
        for (int o = 16; o > 0; o >>= 1) a += __shfl_down_sync(0xFFFFFFFFu, a, o);
        if (t == 0) sh[0] = a;
    }
    __syncthreads();
    int off = sh[0];

    int idx = blk * SCAN_TPB + t;
    if (which) g_baseB[idx] += off;
    else       g_baseA[idx] += off;
}

// K4: place edges into CSR slots — deterministic, NO atomics.
__global__ void k_place(const int* __restrict__ src,
                        const int* __restrict__ dst,
                        const int* __restrict__ ef,
                        int n_edges) {
    int e = blockIdx.x * blockDim.x + threadIdx.x;
    if (e >= n_edges) return;
    int s = src[e], d = dst[e], t = ef[e];
    int r = g_rank[e];
    int two = (t == 0) | (t == 4) | (t == 5);
    g_eA[g_baseA[d] + (r & 0xFFFF)] = (s << 1) | two;
    if (t == 3)
        g_eB[g_baseB[d] + (r >> 16)] = s;
}

// K5: pull two-hop. 16 lanes per node, each lane owns one float4 of the row.
__global__ void k_gather_twohop(int n_nodes) {
    int gid  = blockIdx.x * blockDim.x + threadIdx.x;
    int node = gid >> 4;
    if (node >= n_nodes) return;
    int lane = gid & 15;
    int base = g_baseA[node];
    int cnt  = g_cnt[node];
    float4 acc = make_float4(0.f, 0.f, 0.f, 0.f);
    #pragma unroll 4
    for (int k = 0; k < cnt; k++) {
        int packed = g_eA[base + k];
        float scale = 1.0f + (float)(packed & 1);
        int s = packed >> 1;
        float4 v = *reinterpret_cast<const float4*>(g_emb + (size_t)s * DIM + lane * 4);
        acc.x += v.x * scale; acc.y += v.y * scale;
        acc.z += v.z * scale; acc.w += v.w * scale;
    }
    *reinterpret_cast<float4*>(g_twohop + (size_t)node * DIM + lane * 4) = acc;
}

// K6: pull one-hop (e==3): out[node] = sum twohop[src]. Writes every row.
__global__ void k_gather_onehop(float* __restrict__ out, int n_nodes) {
    int gid  = blockIdx.x * blockDim.x + threadIdx.x;
    int node = gid >> 4;
    if (node >= n_nodes) return;
    int lane = gid & 15;
    int base = g_baseB[node];
    int cnt  = g_cnt[NPAD + node];
    float4 acc = make_float4(0.f, 0.f, 0.f, 0.f);
    #pragma unroll 4
    for (int k = 0; k < cnt; k++) {
        int s = g_eB[base + k];
        float4 v = *reinterpret_cast<const float4*>(g_twohop + (size_t)s * DIM + lane * 4);
        acc.x += v.x; acc.y += v.y; acc.z += v.z; acc.w += v.w;
    }
    *reinterpret_cast<float4*>(out + (size_t)node * DIM + lane * 4) = acc;
}

extern "C" void kernel_launch(void* const* d_in, const int* in_sizes, int n_in,
                              void* d_out, int out_size) {
    const float* x   = (const float*)d_in[0];   // graph_embedding [N, D]
    const float* w   = (const float*)d_in[1];   // weight [1, D]
    const int*   src = (const int*)d_in[2];     // [E]
    const int*   dst = (const int*)d_in[3];     // [E]
    const int*   ef  = (const int*)d_in[4];     // [E]
    float* out = (float*)d_out;                 // [N, D]

    int total   = in_sizes[0];                  // N * D
    int n_edges = in_sizes[2];                  // E
    int n_nodes = total / DIM;
    int total4  = total / 4;
    int nblk    = (n_nodes + SCAN_TPB - 1) / SCAN_TPB;

    const int T = 256;

    // Zero counters via a memset node.
    void* cnt_ptr = nullptr;
    cudaGetSymbolAddress(&cnt_ptr, g_cnt);
    cudaMemsetAsync(cnt_ptr, 0, 2 * NPAD * sizeof(int));

    // K1: emb + fused edge counting with rank capture
    {
        int work = (total4 > n_edges) ? total4 : n_edges;
        k_emb_count<<<(work + T - 1) / T, T>>>((const float4*)x, (const float4*)w,
                                               dst, ef, total4, n_edges);
    }
    // K2/K3: scan (both CSRs)
    k_scan1<<<2 * nblk, SCAN_TPB>>>(nblk);
    k_scan2<<<2 * nblk, SCAN_TPB>>>(nblk);
    // K4: deterministic placement
    k_place<<<(n_edges + T - 1) / T, T>>>(src, dst, ef, n_edges);
    // K5/K6: pull gathers (16 lanes per node)
    {
        int threads = n_nodes * 16;
        k_gather_twohop<<<(threads + T - 1) / T, T>>>(n_nodes);
        k_gather_onehop<<<(threads + T - 1) / T, T>>>(out, n_nodes);
    }
}